// round 12
// baseline (speedup 1.0000x reference)
#include <cuda_runtime.h>
#include <cuda_fp16.h>
#include <cstdint>

// ---------------- problem constants ----------------
#define D_M   8192      // B*S
#define D_K   4096
#define D_N   11008

#define BM    64
#define BN    128
#define BK    64        // 64 fp16 = 128B rows (SW128 atom)
#define KITERS (D_K / BK)   // 64
#define NS    3             // pipeline stages

static constexpr int MT = D_M / BM;   // 128
static constexpr int NT = D_N / BN;   // 86

static constexpr int A_TILE_BYTES = BM * BK * 2;  // 8192
static constexpr int B_TILE_BYTES = BN * BK * 2;  // 16384

static constexpr int NTHREADS = 128;  // 4 warps: 2(M) x 2(N), warp tile 32x64

// smem layout (per CTA ~73 KB -> 3 CTAs/SM)
static constexpr int SM_FULL  = 0;                    // NS * 8
static constexpr int SM_EMPTY = SM_FULL + NS * 8;     // 24
static constexpr int SM_BIAS  = 128;                  // BN floats = 512B
static constexpr int SM_A     = 1024;                              // 1024-aligned
static constexpr int SM_B     = SM_A + NS * A_TILE_BYTES;          // 25600
static constexpr int SMEM_TOTAL = SM_B + NS * B_TILE_BYTES;        // 74752

// ---------------- scratch (tiled, pre-swizzled fp16) ----------------
__device__ __align__(1024) __half g_xt[(size_t)D_M * D_K];   // 64 MiB
__device__ __align__(1024) __half g_wt[(size_t)D_N * D_K];   // 86 MiB

// ---------------- PTX helpers ----------------
__device__ __forceinline__ uint32_t smem_u32(const void* p) {
    uint32_t a;
    asm("{ .reg .u64 t; cvta.to.shared.u64 t, %1; cvt.u32.u64 %0, t; }" : "=r"(a) : "l"(p));
    return a;
}
__device__ __forceinline__ uint32_t elect_one() {
    uint32_t p;
    asm volatile("{ .reg .pred p; elect.sync _|p, 0xFFFFFFFF; selp.b32 %0, 1, 0, p; }" : "=r"(p));
    return p;
}
#define MBAR_INIT(a, cnt) \
    asm volatile("mbarrier.init.shared.b64 [%0], %1;" :: "r"(a), "r"((uint32_t)(cnt)) : "memory")
#define MBAR_EXPECT_TX(a, b) \
    asm volatile("mbarrier.arrive.expect_tx.shared.b64 _, [%0], %1;" :: "r"(a), "r"((uint32_t)(b)) : "memory")
#define MBAR_ARRIVE(a) \
    asm volatile("mbarrier.arrive.shared.b64 _, [%0];" :: "r"(a) : "memory")

#define MBAR_WAIT(a, ph) do {                                                   \
    uint32_t _m = (a); uint32_t _p = (uint32_t)(ph); uint32_t _d;               \
    asm volatile("{ .reg .pred p; mbarrier.try_wait.parity.acquire.cta.shared::cta.b64 p, [%1], %2; selp.b32 %0,1,0,p; }" \
        : "=r"(_d) : "r"(_m), "r"(_p) : "memory");                              \
    if (!_d) { asm volatile("{ .reg .pred P1; WL%=:\n\t"                        \
        "mbarrier.try_wait.parity.acquire.cta.shared::cta.b64 P1, [%0], %1, 0x989680;\n\t" \
        "@P1 bra.uni WD%=;\n\t bra.uni WL%=;\n\t WD%=: }"                       \
        :: "r"(_m), "r"(_p) : "memory"); }                                      \
} while (0)

// Relaxed wait: ONLY for producer empty-waits (post-wait SMEM accesses are
// all async-proxy cp.async.bulk, ordered by their own mechanism).
#define MBAR_WAIT_RELAXED(a, ph) do {                                           \
    uint32_t _m = (a); uint32_t _p = (uint32_t)(ph); uint32_t _d;               \
    asm volatile("{ .reg .pred p; mbarrier.try_wait.parity.relaxed.cta.shared::cta.b64 p, [%1], %2, 0x989680; selp.b32 %0,1,0,p; }" \
        : "=r"(_d) : "r"(_m), "r"(_p) : "memory");                              \
    if (!_d) { asm volatile("{ .reg .pred P1; WL%=:\n\t"                        \
        "mbarrier.try_wait.parity.relaxed.cta.shared::cta.b64 P1, [%0], %1, 0x989680;\n\t" \
        "@P1 bra.uni WD%=;\n\t bra.uni WL%=;\n\t WD%=: }"                       \
        :: "r"(_m), "r"(_p) : "memory"); }                                      \
} while (0)

__device__ __forceinline__ void bulk_g2s(uint32_t dst, const void* src, uint32_t bytes, uint32_t mbar) {
    asm volatile("cp.async.bulk.shared::cta.global.mbarrier::complete_tx::bytes [%0], [%1], %2, [%3];"
        :: "r"(dst), "l"(src), "r"(bytes), "r"(mbar) : "memory");
}

__device__ __forceinline__ void ldmx4(uint32_t& r0, uint32_t& r1, uint32_t& r2, uint32_t& r3, uint32_t a) {
    asm volatile("ldmatrix.sync.aligned.m8n8.x4.shared.b16 {%0,%1,%2,%3}, [%4];"
        : "=r"(r0), "=r"(r1), "=r"(r2), "=r"(r3) : "r"(a));
}

__device__ __forceinline__ void mma16816(float* c, const uint32_t* a, uint32_t b0, uint32_t b1) {
    asm volatile("mma.sync.aligned.m16n8k16.row.col.f32.f16.f16.f32 "
        "{%0,%1,%2,%3}, {%4,%5,%6,%7}, {%8,%9}, {%0,%1,%2,%3};"
        : "+f"(c[0]), "+f"(c[1]), "+f"(c[2]), "+f"(c[3])
        : "r"(a[0]), "r"(a[1]), "r"(a[2]), "r"(a[3]), "r"(b0), "r"(b1));
}

__device__ __forceinline__ uint32_t swz(uint32_t off) { return off ^ ((off >> 3) & 0x70); }

// ---------------- fused converter kernel (pre-swizzled fp16 tiles) ----------------
// float4/int4 vectorized: 16B loads, 8B swizzled stores (swizzle XOR flips
// bits 4-6 only, so 8B-aligned stores remain contiguous).
__global__ void conv_kernel(const float* __restrict__ x, const int* __restrict__ qw,
                            const float* __restrict__ zp_p,
                            __half* __restrict__ xt, __half* __restrict__ wt) {
    int b = blockIdx.x;
    if (b < MT * KITERS) {
        int mt = b / KITERS, kc = b % KITERS;
        const float4* src = (const float4*)(x + (size_t)mt * BM * D_K + (size_t)kc * BK);
        char* dst = (char*)(xt + (size_t)b * (BM * BK));
        for (int i = threadIdx.x; i < BM * BK / 4; i += blockDim.x) {
            int row = i >> 4, c4 = i & 15;      // 16 float4 per 64-elem row
            float4 v = src[(size_t)row * (D_K / 4) + c4];
            __half2 h0 = __floats2half2_rn(v.x, v.y);
            __half2 h1 = __floats2half2_rn(v.z, v.w);
            uint32_t off = swz(row * 128 + c4 * 8);
            *(uint2*)(dst + off) = make_uint2(*(uint32_t*)&h0, *(uint32_t*)&h1);
        }
    } else {
        int t = b - MT * KITERS;
        float zp = *zp_p;
        int nt = t / KITERS, kc = t % KITERS;
        const int4* src = (const int4*)(qw + (size_t)nt * BN * D_K + (size_t)kc * BK);
        char* dst = (char*)(wt + (size_t)t * (BN * BK));
        for (int i = threadIdx.x; i < BN * BK / 4; i += blockDim.x) {
            int row = i >> 4, c4 = i & 15;
            int4 q = src[(size_t)row * (D_K / 4) + c4];
            __half2 h0 = __floats2half2_rn((float)q.x - zp, (float)q.y - zp);
            __half2 h1 = __floats2half2_rn((float)q.z - zp, (float)q.w - zp);
            uint32_t off = swz(row * 128 + c4 * 8);
            *(uint2*)(dst + off) = make_uint2(*(uint32_t*)&h0, *(uint32_t*)&h1);
        }
    }
}

// ---------------- stage body: S is a compile-time stage index ----------------
// Mainloop iteration for stage slot S. All smem bases/slots constant-folded.
// Protocol identical to R10: full(s) was waited by the PREVIOUS body's kk==3
// cross-stage prefetch (or the prologue prime for it==0); empty-arrive goes
// strictly after all MMAs; producer (tid 0) refills with relaxed empty-wait.
template<int S>
__device__ __forceinline__ void stage_body(
    int it, int ph, int tid, uint32_t sb,
    const uint32_t (&aoff)[2], const uint32_t (&boff)[4],
    uint32_t (&afr)[2][2][4], uint32_t (&bfr)[2][4][4],
    float (&acc)[2][4][2][4],
    const char* asrc, const char* bsrc)
{
    constexpr int SN = (S + 1 == NS) ? 0 : S + 1;
    const int phn = (S + 1 == NS) ? (ph ^ 1) : ph;
    constexpr uint32_t AB = SM_A + S * A_TILE_BYTES;
    constexpr uint32_t BB = SM_B + S * B_TILE_BYTES;
    constexpr uint32_t ABN = SM_A + SN * A_TILE_BYTES;
    constexpr uint32_t BBN = SM_B + SN * B_TILE_BYTES;

    #pragma unroll
    for (int kk = 0; kk < 4; kk++) {
        int cur = kk & 1, nxt = cur ^ 1;
        if (kk < 3) {                   // prefetch kk+1 of current stage
            uint32_t kx = (uint32_t)((kk + 1) << 5);
            #pragma unroll
            for (int mi = 0; mi < 2; mi++)
                ldmx4(afr[nxt][mi][0], afr[nxt][mi][1], afr[nxt][mi][2], afr[nxt][mi][3],
                      sb + AB + (aoff[mi] ^ kx));
            #pragma unroll
            for (int gg = 0; gg < 4; gg++)
                ldmx4(bfr[nxt][gg][0], bfr[nxt][gg][1], bfr[nxt][gg][2], bfr[nxt][gg][3],
                      sb + BB + (boff[gg] ^ kx));
        } else if (it + 1 < KITERS) {
            // cross-stage prefetch: wait next stage full, load its kk0
            // fragments (into buf0) BEFORE this stage's final MMA block.
            MBAR_WAIT(sb + SM_FULL + SN * 8, phn);
            #pragma unroll
            for (int mi = 0; mi < 2; mi++)
                ldmx4(afr[nxt][mi][0], afr[nxt][mi][1], afr[nxt][mi][2], afr[nxt][mi][3],
                      sb + ABN + aoff[mi]);
            #pragma unroll
            for (int gg = 0; gg < 4; gg++)
                ldmx4(bfr[nxt][gg][0], bfr[nxt][gg][1], bfr[nxt][gg][2], bfr[nxt][gg][3],
                      sb + BBN + boff[gg]);
        }
        #pragma unroll
        for (int mi = 0; mi < 2; mi++)
            #pragma unroll
            for (int gg = 0; gg < 4; gg++) {
                mma16816(acc[mi][gg][0], afr[cur][mi], bfr[cur][gg][0], bfr[cur][gg][2]);
                mma16816(acc[mi][gg][1], afr[cur][mi], bfr[cur][gg][1], bfr[cur][gg][3]);
            }
    }

    // release the slot only after ALL MMAs of this stage
    if (elect_one()) MBAR_ARRIVE(sb + SM_EMPTY + S * 8);

    if (tid == 0 && it + NS < KITERS) {
        MBAR_WAIT_RELAXED(sb + SM_EMPTY + S * 8, ph);
        int nx = it + NS;
        MBAR_EXPECT_TX(sb + SM_FULL + S * 8, A_TILE_BYTES + B_TILE_BYTES);
        bulk_g2s(sb + AB, asrc + (size_t)nx * A_TILE_BYTES, A_TILE_BYTES, sb + SM_FULL + S * 8);
        bulk_g2s(sb + BB, bsrc + (size_t)nx * B_TILE_BYTES, B_TILE_BYTES, sb + SM_FULL + S * 8);
    }
}

// ---------------- main GEMM kernel ----------------
// 128 threads, 4 warps in 2(M) x 2(N); warp tile 32 x 64. 3 CTAs / SM.
// Mainloop unrolled by NS=3 with compile-time stage slots (no dynamic cursor).
__global__ void __launch_bounds__(NTHREADS, 3)
gemm_kernel(const float* __restrict__ scale_p, const float* __restrict__ bias,
            float* __restrict__ out) {
    extern __shared__ char smem[];
    uint32_t sb = smem_u32(smem);
    int tid = threadIdx.x, wid = tid >> 5, lane = tid & 31;
    int wm = wid & 1;          // 0..1  (M)
    int wn = wid >> 1;         // 0..1  (N)

    // tile decode with M-group swizzle for L2 reuse
    const int GROUP = 16;
    int bid = blockIdx.x;
    int tpg = GROUP * NT;
    int g = bid / tpg, r = bid % tpg;
    int mt = g * GROUP + (r % GROUP);
    int nt = r / GROUP;

    if (tid == 0) {
        for (int s = 0; s < NS; s++) {
            MBAR_INIT(sb + SM_FULL  + s * 8, 1);
            MBAR_INIT(sb + SM_EMPTY + s * 8, 4);
        }
    }
    for (int i = tid; i < BN; i += NTHREADS)
        ((float*)(smem + SM_BIAS))[i] = bias[(size_t)nt * BN + i];
    __syncthreads();

    const char* asrc = (const char*)g_xt + (size_t)mt * KITERS * A_TILE_BYTES;
    const char* bsrc = (const char*)g_wt + (size_t)nt * KITERS * B_TILE_BYTES;

    // prologue: fill all NS stages
    if (tid == 0) {
        for (int s = 0; s < NS; s++) {
            MBAR_EXPECT_TX(sb + SM_FULL + s * 8, A_TILE_BYTES + B_TILE_BYTES);
            bulk_g2s(sb + SM_A + s * A_TILE_BYTES, asrc + (size_t)s * A_TILE_BYTES,
                     A_TILE_BYTES, sb + SM_FULL + s * 8);
            bulk_g2s(sb + SM_B + s * B_TILE_BYTES, bsrc + (size_t)s * B_TILE_BYTES,
                     B_TILE_BYTES, sb + SM_FULL + s * 8);
        }
    }

    // per-lane ldmatrix addressing: hoisted swizzled bases.
    // Pre-swizzle offsets have bits 5-6 == 0 (lcb is bit 4 only), so
    // swz(off + kk*32) == swz(off) XOR (kk*32).
    int lrow = (lane & 7) + ((lane >> 3) & 1) * 8;   // 0..15 within 16-row block
    int lcb  = (lane >> 4) * 16;                     // 0 or 16 bytes (k half)
    uint32_t aoff[2], boff[4];
    #pragma unroll
    for (int mi = 0; mi < 2; mi++)
        aoff[mi] = swz((uint32_t)(wm * 32 + mi * 16 + lrow) * 128 + lcb);
    #pragma unroll
    for (int gg = 0; gg < 4; gg++)
        boff[gg] = swz((uint32_t)(wn * 64 + gg * 16 + lrow) * 128 + lcb);

    float acc[2][4][2][4];    // [mi][gg][sub][4] = 64 f32
    #pragma unroll
    for (int i = 0; i < 2; i++)
        #pragma unroll
        for (int j = 0; j < 4; j++)
            #pragma unroll
            for (int k = 0; k < 2; k++)
                #pragma unroll
                for (int l = 0; l < 4; l++) acc[i][j][k][l] = 0.f;

    uint32_t afr[2][2][4], bfr[2][4][4];   // double-buffered fragments

    // ---- prologue prime: wait stage 0, load its kk0 fragments into buf 0 ----
    MBAR_WAIT(sb + SM_FULL + 0 * 8, 0);
    {
        #pragma unroll
        for (int mi = 0; mi < 2; mi++)
            ldmx4(afr[0][mi][0], afr[0][mi][1], afr[0][mi][2], afr[0][mi][3],
                  sb + SM_A + aoff[mi]);
        #pragma unroll
        for (int gg = 0; gg < 4; gg++)
            ldmx4(bfr[0][gg][0], bfr[0][gg][1], bfr[0][gg][2], bfr[0][gg][3],
                  sb + SM_B + boff[gg]);
    }

    // ---- mainloop: 21 triples + 1 remainder (KITERS = 64 = 3*21 + 1) ----
    int ph = 0;
    #pragma unroll 1
    for (int u = 0; u < KITERS / 3; ++u) {   // 21 iterations
        int itb = u * 3;
        stage_body<0>(itb,     ph, tid, sb, aoff, boff, afr, bfr, acc, asrc, bsrc);
        stage_body<1>(itb + 1, ph, tid, sb, aoff, boff, afr, bfr, acc, asrc, bsrc);
        stage_body<2>(itb + 2, ph, tid, sb, aoff, boff, afr, bfr, acc, asrc, bsrc);
        ph ^= 1;
    }
    // it = 63 runs stage slot 0 at ph = 1 (21 flips)
    stage_body<0>(KITERS - 1, ph, tid, sb, aoff, boff, afr, bfr, acc, asrc, bsrc);

    // ---- epilogue ----
    float scl = *scale_p;
    const float* bs = (const float*)(smem + SM_BIAS);
    int qrow = lane >> 2;          // 0..7
    int qcol = (lane & 3) * 2;     // 0,2,4,6
    #pragma unroll
    for (int mi = 0; mi < 2; mi++) {
        #pragma unroll
        for (int gg = 0; gg < 4; gg++) {
            #pragma unroll
            for (int sub = 0; sub < 2; sub++) {
                int ncol = wn * 64 + gg * 16 + sub * 8 + qcol;       // local in BN
                int m0   = mt * BM + wm * 32 + mi * 16 + qrow;
                size_t og = (size_t)m0 * D_N + (size_t)nt * BN + ncol;
                float b0 = bs[ncol], b1 = bs[ncol + 1];
                float2 v0, v1;
                v0.x = fmaf(scl, acc[mi][gg][sub][0], b0);
                v0.y = fmaf(scl, acc[mi][gg][sub][1], b1);
                v1.x = fmaf(scl, acc[mi][gg][sub][2], b0);
                v1.y = fmaf(scl, acc[mi][gg][sub][3], b1);
                *(float2*)(out + og) = v0;
                *(float2*)(out + og + (size_t)8 * D_N) = v1;
            }
        }
    }
}

// ---------------- launch ----------------
extern "C" void kernel_launch(void* const* d_in, const int* in_sizes, int n_in,
                              void* d_out, int out_size) {
    const float* x     = (const float*)d_in[0];
    const int*   qw    = (const int*)d_in[1];
    const float* scale = (const float*)d_in[2];
    const float* zp    = (const float*)d_in[3];
    const float* bias  = (const float*)d_in[4];
    float* out = (float*)d_out;

    __half* xt; cudaGetSymbolAddress((void**)&xt, g_xt);
    __half* wt; cudaGetSymbolAddress((void**)&wt, g_wt);

    cudaFuncSetAttribute(gemm_kernel, cudaFuncAttributeMaxDynamicSharedMemorySize, SMEM_TOTAL);

    conv_kernel<<<MT * KITERS + NT * KITERS, 256>>>(x, qw, zp, xt, wt);
    gemm_kernel<<<MT * NT, NTHREADS, SMEM_TOTAL>>>(scale, bias, out);
}

// round 13
// speedup vs baseline: 1.4352x; 1.4352x over previous
#include <cuda_runtime.h>
#include <cuda_fp16.h>
#include <cstdint>

// ---------------- problem constants ----------------
#define D_M   8192      // B*S
#define D_K   4096
#define D_N   11008

#define BM    64
#define BN    128
#define BK    64        // 64 fp16 = 128B rows (SW128 atom)
#define KITERS (D_K / BK)   // 64
#define NS    3             // pipeline stages (explicit cursor)

static constexpr int MT = D_M / BM;   // 128
static constexpr int NT = D_N / BN;   // 86

static constexpr int A_TILE_BYTES = BM * BK * 2;  // 8192
static constexpr int B_TILE_BYTES = BN * BK * 2;  // 16384

static constexpr int NTHREADS = 128;  // 4 warps: 2(M) x 2(N), warp tile 32x64

// smem layout (per CTA ~73 KB -> 3 CTAs/SM)
static constexpr int SM_FULL  = 0;                    // NS * 8
static constexpr int SM_EMPTY = SM_FULL + NS * 8;     // 24
static constexpr int SM_BIAS  = 128;                  // BN floats = 512B
static constexpr int SM_A     = 1024;                              // 1024-aligned
static constexpr int SM_B     = SM_A + NS * A_TILE_BYTES;          // 25600
static constexpr int SMEM_TOTAL = SM_B + NS * B_TILE_BYTES;        // 74752

// ---------------- scratch (tiled, pre-swizzled fp16) ----------------
__device__ __align__(1024) __half g_xt[(size_t)D_M * D_K];   // 64 MiB
__device__ __align__(1024) __half g_wt[(size_t)D_N * D_K];   // 86 MiB

// ---------------- PTX helpers ----------------
__device__ __forceinline__ uint32_t smem_u32(const void* p) {
    uint32_t a;
    asm("{ .reg .u64 t; cvta.to.shared.u64 t, %1; cvt.u32.u64 %0, t; }" : "=r"(a) : "l"(p));
    return a;
}
__device__ __forceinline__ uint32_t elect_one() {
    uint32_t p;
    asm volatile("{ .reg .pred p; elect.sync _|p, 0xFFFFFFFF; selp.b32 %0, 1, 0, p; }" : "=r"(p));
    return p;
}
#define MBAR_INIT(a, cnt) \
    asm volatile("mbarrier.init.shared.b64 [%0], %1;" :: "r"(a), "r"((uint32_t)(cnt)) : "memory")
#define MBAR_EXPECT_TX(a, b) \
    asm volatile("mbarrier.arrive.expect_tx.shared.b64 _, [%0], %1;" :: "r"(a), "r"((uint32_t)(b)) : "memory")
#define MBAR_ARRIVE(a) \
    asm volatile("mbarrier.arrive.shared.b64 _, [%0];" :: "r"(a) : "memory")

#define MBAR_WAIT(a, ph) do {                                                   \
    uint32_t _m = (a); uint32_t _p = (uint32_t)(ph); uint32_t _d;               \
    asm volatile("{ .reg .pred p; mbarrier.try_wait.parity.acquire.cta.shared::cta.b64 p, [%1], %2; selp.b32 %0,1,0,p; }" \
        : "=r"(_d) : "r"(_m), "r"(_p) : "memory");                              \
    if (!_d) { asm volatile("{ .reg .pred P1; WL%=:\n\t"                        \
        "mbarrier.try_wait.parity.acquire.cta.shared::cta.b64 P1, [%0], %1, 0x989680;\n\t" \
        "@P1 bra.uni WD%=;\n\t bra.uni WL%=;\n\t WD%=: }"                       \
        :: "r"(_m), "r"(_p) : "memory"); }                                      \
} while (0)

__device__ __forceinline__ void bulk_g2s(uint32_t dst, const void* src, uint32_t bytes, uint32_t mbar) {
    asm volatile("cp.async.bulk.shared::cta.global.mbarrier::complete_tx::bytes [%0], [%1], %2, [%3];"
        :: "r"(dst), "l"(src), "r"(bytes), "r"(mbar) : "memory");
}

__device__ __forceinline__ void ldmx4(uint32_t& r0, uint32_t& r1, uint32_t& r2, uint32_t& r3, uint32_t a) {
    asm volatile("ldmatrix.sync.aligned.m8n8.x4.shared.b16 {%0,%1,%2,%3}, [%4];"
        : "=r"(r0), "=r"(r1), "=r"(r2), "=r"(r3) : "r"(a));
}

__device__ __forceinline__ void mma16816(float* c, const uint32_t* a, uint32_t b0, uint32_t b1) {
    asm volatile("mma.sync.aligned.m16n8k16.row.col.f32.f16.f16.f32 "
        "{%0,%1,%2,%3}, {%4,%5,%6,%7}, {%8,%9}, {%0,%1,%2,%3};"
        : "+f"(c[0]), "+f"(c[1]), "+f"(c[2]), "+f"(c[3])
        : "r"(a[0]), "r"(a[1]), "r"(a[2]), "r"(a[3]), "r"(b0), "r"(b1));
}

__device__ __forceinline__ uint32_t swz(uint32_t off) { return off ^ ((off >> 3) & 0x70); }

// ---------------- fused converter kernel (pre-swizzled fp16 tiles) ----------------
// float4/int4 vectorized: 16B loads, 8B swizzled stores (swizzle XOR flips
// bits 4-6 only, so 8B-aligned stores remain contiguous).
__global__ void conv_kernel(const float* __restrict__ x, const int* __restrict__ qw,
                            const float* __restrict__ zp_p,
                            __half* __restrict__ xt, __half* __restrict__ wt) {
    int b = blockIdx.x;
    if (b < MT * KITERS) {
        int mt = b / KITERS, kc = b % KITERS;
        const float4* src = (const float4*)(x + (size_t)mt * BM * D_K + (size_t)kc * BK);
        char* dst = (char*)(xt + (size_t)b * (BM * BK));
        for (int i = threadIdx.x; i < BM * BK / 4; i += blockDim.x) {
            int row = i >> 4, c4 = i & 15;      // 16 float4 per 64-elem row
            float4 v = src[(size_t)row * (D_K / 4) + c4];
            __half2 h0 = __floats2half2_rn(v.x, v.y);
            __half2 h1 = __floats2half2_rn(v.z, v.w);
            uint32_t off = swz(row * 128 + c4 * 8);
            *(uint2*)(dst + off) = make_uint2(*(uint32_t*)&h0, *(uint32_t*)&h1);
        }
    } else {
        int t = b - MT * KITERS;
        float zp = *zp_p;
        int nt = t / KITERS, kc = t % KITERS;
        const int4* src = (const int4*)(qw + (size_t)nt * BN * D_K + (size_t)kc * BK);
        char* dst = (char*)(wt + (size_t)t * (BN * BK));
        for (int i = threadIdx.x; i < BN * BK / 4; i += blockDim.x) {
            int row = i >> 4, c4 = i & 15;
            int4 q = src[(size_t)row * (D_K / 4) + c4];
            __half2 h0 = __floats2half2_rn((float)q.x - zp, (float)q.y - zp);
            __half2 h1 = __floats2half2_rn((float)q.z - zp, (float)q.w - zp);
            uint32_t off = swz(row * 128 + c4 * 8);
            *(uint2*)(dst + off) = make_uint2(*(uint32_t*)&h0, *(uint32_t*)&h1);
        }
    }
}

// ---------------- main GEMM kernel (R10 winner, byte-for-byte) ----------------
// 128 threads, 4 warps in 2(M) x 2(N); warp tile 32 x 64. 3 CTAs / SM.
// Cross-stage fragment prefetch: at kk==3 the warp waits full(s+1) and
// LDSM-prefetches stage s+1's kk0 fragments BEFORE the final MMA block.
// Compact dynamic-cursor mainloop (code size kept small: DVFS/I$ lesson, R12).
__global__ void __launch_bounds__(NTHREADS, 3)
gemm_kernel(const float* __restrict__ scale_p, const float* __restrict__ bias,
            float* __restrict__ out) {
    extern __shared__ char smem[];
    uint32_t sb = smem_u32(smem);
    int tid = threadIdx.x, wid = tid >> 5, lane = tid & 31;
    int wm = wid & 1;          // 0..1  (M)
    int wn = wid >> 1;         // 0..1  (N)

    // tile decode with M-group swizzle for L2 reuse
    const int GROUP = 16;
    int bid = blockIdx.x;
    int tpg = GROUP * NT;
    int g = bid / tpg, r = bid % tpg;
    int mt = g * GROUP + (r % GROUP);
    int nt = r / GROUP;

    if (tid == 0) {
        for (int s = 0; s < NS; s++) {
            MBAR_INIT(sb + SM_FULL  + s * 8, 1);
            MBAR_INIT(sb + SM_EMPTY + s * 8, 4);
        }
    }
    for (int i = tid; i < BN; i += NTHREADS)
        ((float*)(smem + SM_BIAS))[i] = bias[(size_t)nt * BN + i];
    __syncthreads();

    const char* asrc = (const char*)g_xt + (size_t)mt * KITERS * A_TILE_BYTES;
    const char* bsrc = (const char*)g_wt + (size_t)nt * KITERS * B_TILE_BYTES;

    // prologue: fill all NS stages
    if (tid == 0) {
        for (int s = 0; s < NS; s++) {
            MBAR_EXPECT_TX(sb + SM_FULL + s * 8, A_TILE_BYTES + B_TILE_BYTES);
            bulk_g2s(sb + SM_A + s * A_TILE_BYTES, asrc + (size_t)s * A_TILE_BYTES,
                     A_TILE_BYTES, sb + SM_FULL + s * 8);
            bulk_g2s(sb + SM_B + s * B_TILE_BYTES, bsrc + (size_t)s * B_TILE_BYTES,
                     B_TILE_BYTES, sb + SM_FULL + s * 8);
        }
    }

    // per-lane ldmatrix addressing: hoisted swizzled bases.
    // Pre-swizzle offsets have bits 5-6 == 0 (lcb is bit 4 only), so
    // swz(off + kk*32) == swz(off) XOR (kk*32).
    int lrow = (lane & 7) + ((lane >> 3) & 1) * 8;   // 0..15 within 16-row block
    int lcb  = (lane >> 4) * 16;                     // 0 or 16 bytes (k half)
    uint32_t aoff[2], boff[4];
    #pragma unroll
    for (int mi = 0; mi < 2; mi++)
        aoff[mi] = swz((uint32_t)(wm * 32 + mi * 16 + lrow) * 128 + lcb);
    #pragma unroll
    for (int gg = 0; gg < 4; gg++)
        boff[gg] = swz((uint32_t)(wn * 64 + gg * 16 + lrow) * 128 + lcb);

    float acc[2][4][2][4];    // [mi][gg][sub][4] = 64 f32
    #pragma unroll
    for (int i = 0; i < 2; i++)
        #pragma unroll
        for (int j = 0; j < 4; j++)
            #pragma unroll
            for (int k = 0; k < 2; k++)
                #pragma unroll
                for (int l = 0; l < 4; l++) acc[i][j][k][l] = 0.f;

    uint32_t afr[2][2][4], bfr[2][4][4];   // double-buffered fragments

    // ---- prologue prime: wait stage 0, load its kk0 fragments into buf 0 ----
    MBAR_WAIT(sb + SM_FULL + 0 * 8, 0);
    {
        uint32_t abase = sb + SM_A, bbase = sb + SM_B;
        #pragma unroll
        for (int mi = 0; mi < 2; mi++)
            ldmx4(afr[0][mi][0], afr[0][mi][1], afr[0][mi][2], afr[0][mi][3],
                  abase + aoff[mi]);
        #pragma unroll
        for (int gg = 0; gg < 4; gg++)
            ldmx4(bfr[0][gg][0], bfr[0][gg][1], bfr[0][gg][2], bfr[0][gg][3],
                  bbase + boff[gg]);
    }

    int s = 0, ph = 0;   // explicit (stage, phase) cursor: NS == 3
    for (int it = 0; it < KITERS; ++it) {
        uint32_t abase = sb + SM_A + s * A_TILE_BYTES;
        uint32_t bbase = sb + SM_B + s * B_TILE_BYTES;
        int sn  = (s + 1 == NS) ? 0 : s + 1;          // next stage slot
        int phn = (s + 1 == NS) ? (ph ^ 1) : ph;      // next stage phase

        #pragma unroll
        for (int kk = 0; kk < 4; kk++) {
            int cur = kk & 1, nxt = cur ^ 1;
            if (kk < 3) {                   // prefetch kk+1 of current stage
                uint32_t kx = (uint32_t)((kk + 1) << 5);
                #pragma unroll
                for (int mi = 0; mi < 2; mi++)
                    ldmx4(afr[nxt][mi][0], afr[nxt][mi][1], afr[nxt][mi][2], afr[nxt][mi][3],
                          abase + (aoff[mi] ^ kx));
                #pragma unroll
                for (int gg = 0; gg < 4; gg++)
                    ldmx4(bfr[nxt][gg][0], bfr[nxt][gg][1], bfr[nxt][gg][2], bfr[nxt][gg][3],
                          bbase + (boff[gg] ^ kx));
            } else if (it + 1 < KITERS) {
                // cross-stage prefetch: wait next stage full, load its kk0
                // fragments (into buf0) BEFORE this stage's final MMA block.
                MBAR_WAIT(sb + SM_FULL + sn * 8, phn);
                uint32_t abn = sb + SM_A + sn * A_TILE_BYTES;
                uint32_t bbn = sb + SM_B + sn * B_TILE_BYTES;
                #pragma unroll
                for (int mi = 0; mi < 2; mi++)
                    ldmx4(afr[nxt][mi][0], afr[nxt][mi][1], afr[nxt][mi][2], afr[nxt][mi][3],
                          abn + aoff[mi]);
                #pragma unroll
                for (int gg = 0; gg < 4; gg++)
                    ldmx4(bfr[nxt][gg][0], bfr[nxt][gg][1], bfr[nxt][gg][2], bfr[nxt][gg][3],
                          bbn + boff[gg]);
            }
            #pragma unroll
            for (int mi = 0; mi < 2; mi++)
                #pragma unroll
                for (int gg = 0; gg < 4; gg++) {
                    mma16816(acc[mi][gg][0], afr[cur][mi], bfr[cur][gg][0], bfr[cur][gg][2]);
                    mma16816(acc[mi][gg][1], afr[cur][mi], bfr[cur][gg][1], bfr[cur][gg][3]);
                }
        }

        // release the slot only after ALL MMAs of this stage
        if (elect_one()) MBAR_ARRIVE(sb + SM_EMPTY + s * 8);

        if (tid == 0 && it + NS < KITERS) {
            MBAR_WAIT(sb + SM_EMPTY + s * 8, ph);
            int nx = it + NS;
            MBAR_EXPECT_TX(sb + SM_FULL + s * 8, A_TILE_BYTES + B_TILE_BYTES);
            bulk_g2s(sb + SM_A + s * A_TILE_BYTES, asrc + (size_t)nx * A_TILE_BYTES,
                     A_TILE_BYTES, sb + SM_FULL + s * 8);
            bulk_g2s(sb + SM_B + s * B_TILE_BYTES, bsrc + (size_t)nx * B_TILE_BYTES,
                     B_TILE_BYTES, sb + SM_FULL + s * 8);
        }
        s = sn; ph = phn;
    }

    // ---- epilogue ----
    float scl = *scale_p;
    const float* bs = (const float*)(smem + SM_BIAS);
    int qrow = lane >> 2;          // 0..7
    int qcol = (lane & 3) * 2;     // 0,2,4,6
    #pragma unroll
    for (int mi = 0; mi < 2; mi++) {
        #pragma unroll
        for (int gg = 0; gg < 4; gg++) {
            #pragma unroll
            for (int sub = 0; sub < 2; sub++) {
                int ncol = wn * 64 + gg * 16 + sub * 8 + qcol;       // local in BN
                int m0   = mt * BM + wm * 32 + mi * 16 + qrow;
                size_t og = (size_t)m0 * D_N + (size_t)nt * BN + ncol;
                float b0 = bs[ncol], b1 = bs[ncol + 1];
                float2 v0, v1;
                v0.x = fmaf(scl, acc[mi][gg][sub][0], b0);
                v0.y = fmaf(scl, acc[mi][gg][sub][1], b1);
                v1.x = fmaf(scl, acc[mi][gg][sub][2], b0);
                v1.y = fmaf(scl, acc[mi][gg][sub][3], b1);
                *(float2*)(out + og) = v0;
                *(float2*)(out + og + (size_t)8 * D_N) = v1;
            }
        }
    }
}

// ---------------- launch ----------------
extern "C" void kernel_launch(void* const* d_in, const int* in_sizes, int n_in,
                              void* d_out, int out_size) {
    const float* x     = (const float*)d_in[0];
    const int*   qw    = (const int*)d_in[1];
    const float* scale = (const float*)d_in[2];
    const float* zp    = (const float*)d_in[3];
    const float* bias  = (const float*)d_in[4];
    float* out = (float*)d_out;

    __half* xt; cudaGetSymbolAddress((void**)&xt, g_xt);
    __half* wt; cudaGetSymbolAddress((void**)&wt, g_wt);

    cudaFuncSetAttribute(gemm_kernel, cudaFuncAttributeMaxDynamicSharedMemorySize, SMEM_TOTAL);

    conv_kernel<<<MT * KITERS + NT * KITERS, 256>>>(x, qw, zp, xt, wt);
    gemm_kernel<<<MT * NT, NTHREADS, SMEM_TOTAL>>>(scale, bias, out);
}